// round 13
// baseline (speedup 1.0000x reference)
#include <cuda_runtime.h>

// S4 DPLR layer, round 13: fft512q — 4 points/thread, 128 threads/FFT
// (radix-2 + 4x radix-4, 5 stages). Blocks grow to 512 threads for the big
// kernels -> ~27.7 warps/SM (was 13.8; grid=256 is the block-count ceiling).
// Conflict-engineered group strides (68 / 19 / 5); final store is
// lane-consecutive by choosing thread id = accumulated output digits G3.
// Pipeline identical to round-11/12 (half-size real-output inverse).

#define L_SIZE   262144   // 2^18
#define N2L      524288   // 2^19
#define PI2      6.283185307179586f
#define CH       640      // padded smem chunk per 512-pt FFT (float2 units)

__device__ float4 dA4_[N2L/2];    // 4 MB scratch (float4-backed: 16B aligned)
__device__ float4 dB4_[N2L/2];    // 4 MB scratch
#define dA ((float2*)dA4_)
#define dB ((float2*)dB4_)
__device__ float2 gtw512g[512];    // exp(-2pi i k/512)
__device__ float2 gtw1024g[512];   // exp(-2pi i k/1024), k<512

typedef unsigned long long u64c;
#define NEG1P 0xBF800000BF800000ull   // packed (-1.0f, -1.0f)

static __device__ __forceinline__ u64c pk(float2 a) {
    u64c r; asm("mov.b64 %0, {%1, %2};" : "=l"(r) : "f"(a.x), "f"(a.y)); return r;
}
static __device__ __forceinline__ float2 upk(u64c a) {
    float2 r; asm("mov.b64 {%0, %1}, %2;" : "=f"(r.x), "=f"(r.y) : "l"(a)); return r;
}
static __device__ __forceinline__ u64c padd(u64c a, u64c b) {
    u64c r; asm("add.rn.f32x2 %0, %1, %2;" : "=l"(r) : "l"(a), "l"(b)); return r;
}
static __device__ __forceinline__ u64c pfma(u64c a, u64c b, u64c c) {
    u64c r; asm("fma.rn.f32x2 %0, %1, %2, %3;" : "=l"(r) : "l"(a), "l"(b), "l"(c)); return r;
}
static __device__ __forceinline__ u64c psub(u64c a, u64c b) {
    u64c r; asm("fma.rn.f32x2 %0, %1, %2, %3;" : "=l"(r) : "l"(b), "l"((u64c)NEG1P), "l"(a)); return r;
}

static __device__ __forceinline__ float2 cmul(float2 a, float2 b) {
    return make_float2(a.x*b.x - a.y*b.y, a.x*b.y + a.y*b.x);
}
static __device__ __forceinline__ float2 cadd(float2 a, float2 b) {
    return make_float2(a.x + b.x, a.y + b.y);
}
static __device__ __forceinline__ float2 csub(float2 a, float2 b) {
    return make_float2(a.x - b.x, a.y - b.y);
}

// exp(sgn * 2*pi*i * mm / n), mm in [0, n). Centered arg -> __sincosf safe.
static __device__ __forceinline__ float2 twiddle_c(int mm, int n, float sgn) {
    int tt = mm - ((mm >= (n >> 1)) ? n : 0);
    float ang = sgn * (PI2 / (float)n) * (float)tt;
    float s, c; __sincosf(ang, &s, &c);
    return make_float2(c, s);
}

template<int SIGN>
static __device__ __forceinline__ float2 twl(const float2* tw, int idx) {
    float2 w = tw[idx];
    if (SIGN > 0) w.y = -w.y;
    return w;
}
static __device__ __forceinline__ u64c pcmul(u64c a, float2 b) {
    float2 f = upk(a);
    return pk(cmul(f, b));
}
template<int SIGN>
static __device__ __forceinline__ u64c pmulpmi(u64c a) {   // *(-i) fwd, *(+i) inv
    float2 f = upk(a);
    return (SIGN < 0) ? pk(make_float2(f.y, -f.x)) : pk(make_float2(-f.y, f.x));
}

// radix-4 DIT butterfly in registers (packed complex). v in natural order,
// out v[j] = sum_a v_a W4^{a j} (SIGN=-1 fwd, +1 inv).
template<int SIGN>
static __device__ __forceinline__ void r4p(u64c v[4]) {
    u64c t0 = padd(v[0], v[2]), t1 = psub(v[0], v[2]);
    u64c t2 = padd(v[1], v[3]), t3 = pmulpmi<SIGN>(psub(v[1], v[3]));
    v[0] = padd(t0, t2); v[2] = psub(t0, t2);
    v[1] = padd(t1, t3); v[3] = psub(t1, t3);
}

// Named barrier for the 128-thread FFT group f (ids 1..4).
static __device__ __forceinline__ void qbar(int f) {
    asm volatile("bar.sync %0, 128;" :: "r"(f + 1) : "memory");
}

// 512-pt FFT, 128 threads per FFT (l in [0,128)), 4 points/thread, chunk f at
// offset f*CH in both buffers. Natural input A[f*CH+0..511], natural output
// B[f*CH+0..511]; A clobbered. All block threads MUST call (barriers inside);
// `active` masks work only. Caller syncs after filling A.
// Decimation n = 256a + 64b + 16c + 4d + e; output k = j0+2j1+8j2+32j3+128j4.
// Intermediate layouts: y0 @B: 256*j0 + n'; y1 @A: 68*G1 + m (G1=j0+2j1);
// y2 @B: 19*G2 + m2 (G2=G1+8j2); y3 @A: 5*G3 + m3 (G3=G2+32j3); X @B natural.
template<int SIGN>
static __device__ __forceinline__ void fft512q(
    float2* A, float2* B, int f, int l, const float2* tw, bool active)
{
    const int ba = f * CH;
    u64c v[4];
    if (active) {       // stage 0: radix-2 over a (stride 256), 2 butterflies
        #pragma unroll
        for (int h = 0; h < 2; ++h) {
            int np = l + 128*h;
            u64c x0 = pk(A[ba + np]), x1 = pk(A[ba + np + 256]);
            u64c F0 = padd(x0, x1), F1 = psub(x0, x1);
            F1 = pcmul(F1, twl<SIGN>(tw, np));            // W512^{n' * 1}
            B[ba + np]       = upk(F0);
            B[ba + 256 + np] = upk(F1);
        }
    }
    qbar(f);
    {                   // stage 1: thread (j0 = l&1, m = l>>1), radix-4 over b
        const int j0 = l & 1, m = l >> 1;
        if (active) {
            #pragma unroll
            for (int b = 0; b < 4; ++b) v[b] = pk(B[ba + 256*j0 + 64*b + m]);
            r4p<SIGN>(v);
            #pragma unroll
            for (int j1 = 0; j1 < 4; ++j1) {
                if (j1) v[j1] = pcmul(v[j1], twl<SIGN>(tw, 2*m*j1));   // W256^{m j1}
                A[ba + 68*(j0 + 2*j1) + m] = upk(v[j1]);
            }
        }
    }
    qbar(f);
    {                   // stage 2: thread (G1 = l&7, m2 = l>>3), radix-4 over c
        const int G1 = l & 7, m2 = l >> 3;
        if (active) {
            #pragma unroll
            for (int c = 0; c < 4; ++c) v[c] = pk(A[ba + 68*G1 + 16*c + m2]);
            r4p<SIGN>(v);
            #pragma unroll
            for (int j2 = 0; j2 < 4; ++j2) {
                if (j2) v[j2] = pcmul(v[j2], twl<SIGN>(tw, 8*m2*j2));  // W64^{m2 j2}
                B[ba + 19*(G1 + 8*j2) + m2] = upk(v[j2]);
            }
        }
    }
    qbar(f);
    {                   // stage 3: thread (G2 = l&31, m3 = l>>5), radix-4 over d
        const int G2 = l & 31, m3 = l >> 5;
        if (active) {
            #pragma unroll
            for (int d = 0; d < 4; ++d) v[d] = pk(B[ba + 19*G2 + 4*d + m3]);
            r4p<SIGN>(v);
            #pragma unroll
            for (int j3 = 0; j3 < 4; ++j3) {
                if (j3) v[j3] = pcmul(v[j3], twl<SIGN>(tw, 32*m3*j3)); // W16^{m3 j3}
                A[ba + 5*(G2 + 32*j3) + m3] = upk(v[j3]);
            }
        }
    }
    qbar(f);
    if (active) {       // stage 4: thread l = G3, radix-4 over e -> j4
        #pragma unroll
        for (int e = 0; e < 4; ++e) v[e] = pk(A[ba + 5*l + e]);
        r4p<SIGN>(v);
        #pragma unroll
        for (int j4 = 0; j4 < 4; ++j4) B[ba + l + 128*j4] = upk(v[j4]);
    }
    __syncthreads();
}

// ---------------------------------------------------------------------------
// k0: DPLR generator, grid=1024 x 256 (unchanged from R12: packed f32x2 pole
//     loop, pair-batched scaled reciprocals, sincosf Omega for the Nyquist-
//     nonzero property). Blocks 0,1 fill global twiddle tables.
// ---------------------------------------------------------------------------
#define TPB0 256
__global__ void k0_gen(const float* __restrict__ Lre, const float* __restrict__ Lim,
                       const float* __restrict__ Pre, const float* __restrict__ Pim,
                       const float* __restrict__ Bre, const float* __restrict__ Bim,
                       const float* __restrict__ Cri, const float* __restrict__ ls) {
    __shared__ float sLre[64], sLim[64];
    __shared__ u64c  sv[4][64], svs[4][64];
    const int t = threadIdx.x;
    const int b = blockIdx.x;
    if (b == 0) {
        for (int k = t; k < 512; k += TPB0) {
            float s, c; sincospif(-2.0f * (float)k / 512.0f, &s, &c);
            gtw512g[k] = make_float2(c, s);
        }
    } else if (b == 1) {
        for (int k = t; k < 512; k += TPB0) {
            float s, c; sincospif(-2.0f * (float)k / 1024.0f, &s, &c);
            gtw1024g[k] = make_float2(c, s);
        }
    }
    if (t < 64) {
        float2 Pv = make_float2(Pre[t], Pim[t]);
        float2 Bv = make_float2(Bre[t], Bim[t]);
        float2 Cj = make_float2(Cri[2*t], -Cri[2*t+1]);
        float2 Pj = make_float2(Pv.x, -Pv.y);
        sLre[t] = Lre[t]; sLim[t] = Lim[t];
        float2 v0 = cmul(Cj, Bv), v1 = cmul(Cj, Pv);
        float2 v2 = cmul(Pj, Bv), v3 = cmul(Pj, Pv);
        sv[0][t] = pk(v0); svs[0][t] = pk(make_float2(v0.y, v0.x));
        sv[1][t] = pk(v1); svs[1][t] = pk(make_float2(v1.y, v1.x));
        sv[2][t] = pk(v2); svs[2][t] = pk(make_float2(v2.y, v2.x));
        sv[3][t] = pk(v3); svs[3][t] = pk(make_float2(v3.y, v3.x));
    }
    __syncthreads();

    const int k1 = (b & 63) * 8 + (t >> 5);
    const int m  = (b >> 6) * 32 + (t & 31);
    const int j  = k1 + (m << 9);
    const float step = expf(ls[0]);

    float ang = -PI2 * ((float)j / (float)L_SIZE);
    float sn, cs; sincosf(ang, &sn, &cs);
    float2 onem = make_float2(1.f - cs, -sn);
    float2 onep = make_float2(1.f + cs,  sn);
    float invp = 1.f / (onep.x*onep.x + onep.y*onep.y);
    float2 cc = make_float2(2.f*onep.x*invp, -2.f*onep.y*invp);
    float2 qv = cmul(onem, make_float2(onep.x, -onep.y));
    float sfac = (2.f / step) * invp;
    float gx = qv.x * sfac, gy = qv.y * sfac;

    const float S = 5.9604644775390625e-8f;        // 2^-24
    u64c a00 = 0ull, a01 = 0ull, a10 = 0ull, a11 = 0ull;
    #pragma unroll
    for (int q = 0; q < 32; ++q) {
        const int n = 2*q;
        float dx0 = gx - sLre[n],   dy0 = gy - sLim[n];
        float dx1 = gx - sLre[n+1], dy1 = gy - sLim[n+1];
        float b0 = fmaf(dx0, dx0, dy0*dy0) * S;
        float b1 = fmaf(dx1, dx1, dy1*dy1) * S;
        float tq = 1.f / (b0 * b1);
        float i0 = b1 * tq * S;
        float i1 = b0 * tq * S;
        float rx0 = dx0*i0, p0 = dy0*i0;
        float rx1 = dx1*i1, p1 = dy1*i1;
        u64c pa0 = pk(make_float2(rx0,  rx0));
        u64c pb0 = pk(make_float2(p0,  -p0));
        u64c pa1 = pk(make_float2(rx1,  rx1));
        u64c pb1 = pk(make_float2(p1,  -p1));
        a00 = pfma(pa0, sv[0][n], pfma(pb0, svs[0][n], a00));
        a01 = pfma(pa0, sv[1][n], pfma(pb0, svs[1][n], a01));
        a10 = pfma(pa0, sv[2][n], pfma(pb0, svs[2][n], a10));
        a11 = pfma(pa0, sv[3][n], pfma(pb0, svs[3][n], a11));
        a00 = pfma(pa1, sv[0][n+1], pfma(pb1, svs[0][n+1], a00));
        a01 = pfma(pa1, sv[1][n+1], pfma(pb1, svs[1][n+1], a01));
        a10 = pfma(pa1, sv[2][n+1], pfma(pb1, svs[2][n+1], a10));
        a11 = pfma(pa1, sv[3][n+1], pfma(pb1, svs[3][n+1], a11));
    }
    float2 k00 = upk(a00), k01 = upk(a01), k10 = upk(a10), k11 = upk(a11);
    float2 den = make_float2(1.f + k11.x, k11.y);
    float invd = 1.f / (den.x*den.x + den.y*den.y);
    float2 num = cmul(k01, k10);
    float2 tq2 = cmul(num, make_float2(den.x*invd, -den.y*invd));
    float2 at  = cmul(cc, make_float2(k00.x - tq2.x, k00.y - tq2.y));

    dA[k1 * 512 + m] = at;
}

// ---------------------------------------------------------------------------
// k1: IFFT_L row pass (2 rows/block, TPB=256, 2 chunks) + twiddle -> dB.
// ---------------------------------------------------------------------------
#define TPB1 256
__global__ void k1_rowfft() {
    __shared__ __align__(16) float2 sa[2*CH], sb[2*CH];
    __shared__ float2 tw[512];
    const int t = threadIdx.x;
    for (int i = t; i < 512; i += TPB1) tw[i] = gtw512g[i];
    const int row0 = blockIdx.x * 2;
    const float4* src = (const float4*)(dA + row0 * 512);
    for (int i = t; i < 512; i += TPB1) {
        int g = i >> 8, m2 = i & 255;
        float4 x = src[i];
        *(float4*)&sa[g*CH + 2*m2] = x;
    }
    __syncthreads();
    fft512q<+1>(sa, sb, t >> 7, t & 127, tw, true);
    for (int i = t; i < 512; i += TPB1) {
        int g = i >> 8, m2 = i & 255, m = 2*m2;
        int kk = row0 + g;
        float2 y0 = cmul(sb[g*CH + m],     twiddle_c((m*kk) & (L_SIZE-1),     L_SIZE, 1.0f));
        float2 y1 = cmul(sb[g*CH + m + 1], twiddle_c(((m+1)*kk) & (L_SIZE-1), L_SIZE, 1.0f));
        *(float4*)&dB[kk * 512 + m] = make_float4(y0.x, y0.y, y1.x, y1.y);
    }
}

// ---------------------------------------------------------------------------
// k23 FUSED: columns m0, m0+1 (grid=256, TPB=512).
//   Phase A: IFFT512 of dB cols (2 FFTs, t<256) -> K; t>=256 prefetch u.
//   Phase B: z = u + i*K for c = m and c = m+512; 4 fwd FFTs + fwd twiddle
//            -> dA[k1*1024 + c].
// ---------------------------------------------------------------------------
#define TPB23 512
__global__ void k23_cols(const float* __restrict__ u) {
    __shared__ __align__(16) float2 sa[4*CH], sb[4*CH];
    __shared__ float2 tw[512];
    __shared__ float su[4*260];
    const int m0 = blockIdx.x * 2;
    const int t = threadIdx.x;
    for (int i = t; i < 512; i += TPB23) tw[i] = gtw512g[i];
    for (int i = t; i < 512; i += TPB23) {
        float4 x = *(const float4*)(dB + i * 512 + m0);
        sa[0*CH + i] = make_float2(x.x, x.y);
        sa[1*CH + i] = make_float2(x.z, x.w);
    }
    __syncthreads();
    if (t >= 256) {
        for (int i = t - 256; i < 1024; i += 256) {
            int fp = i & 3, rr = i >> 2;
            int c = m0 + (fp & 1) + (fp >> 1) * 512;
            su[fp * 260 + rr] = u[rr * 1024 + c];
        }
    }
    fft512q<+1>(sa, sb, t >> 7, t & 127, tw, t < 256);
    const float invL = 1.0f / (float)L_SIZE;
    for (int i = t; i < 2048; i += TPB23) {
        int fp = i >> 9, rr = i & 511;
        int half = fp >> 1, f = fp & 1;
        float2 z = make_float2(0.f, 0.f);
        if (rr < 256) {
            float kv = sb[f*CH + 2*rr + half].x * invL;
            z = make_float2(su[fp * 260 + rr], kv);
        }
        sa[fp*CH + rr] = z;
    }
    __syncthreads();
    fft512q<-1>(sa, sb, t >> 7, t & 127, tw, true);
    for (int i = t; i < 2048; i += TPB23) {
        int fp = i & 3, k1 = i >> 2;
        int half = fp >> 1, f = fp & 1;
        int c = m0 + f + half * 512;
        int mm = (c * k1) & (N2L - 1);
        dA[k1 * 1024 + c] = cmul(sb[fp*CH + k1], twiddle_c(mm, N2L, -1.0f));
    }
}

// ---------------------------------------------------------------------------
// k4: paired rows (k1, 512-k1); block 0 takes self-paired rows {0,256}.
//   fwd FFT1024 x2 via radix-2 split (chunk fp = slot*2+h holds Z[2r+h]).
//   Pointwise S = U*Kd (Hermitian split). REAL-OUTPUT trick:
//   T[kc] = (S[k]+S[k+L])/2 + i w^k (S[k]-S[k+L])/2, k = rowk1 + 512 kc.
//   One FFT512^{+} per slot on T + W_L^{+m k1} twiddle -> dB[k1*512 + m].
//   grid=256, TPB=512.
// ---------------------------------------------------------------------------
#define TPB4 512
__global__ void k4_mega() {
    __shared__ __align__(16) float2 sa[4*CH], sb[4*CH];
    __shared__ float2 tw[512], twh[512];
    const int t = threadIdx.x;
    for (int i = t; i < 512; i += TPB4) { tw[i] = gtw512g[i]; twh[i] = gtw1024g[i]; }
    const int b = blockIdx.x;
    const int rowA = b;
    const int rowB = (b == 0) ? 256 : 512 - b;

    for (int i = t; i < 1024; i += TPB4) {
        int slot = i >> 9, m2 = i & 511;
        int row = slot ? rowB : rowA;
        float4 x = ((const float4*)(dA + row * 1024))[m2];
        *(float4*)&sb[slot * 1024 + 2*m2] = x;
    }
    __syncthreads();
    for (int i = t; i < 1024; i += TPB4) {
        int slot = i >> 9, m = i & 511;
        float2 a = sb[slot * 1024 + m];
        float2 c = sb[slot * 1024 + m + 512];
        sa[(slot*2 + 0)*CH + m] = cadd(a, c);
        sa[(slot*2 + 1)*CH + m] = cmul(csub(a, c), twh[m]);
    }
    __syncthreads();
    fft512q<-1>(sa, sb, t >> 7, t & 127, tw, true);
    for (int i = t; i < 2048; i += TPB4) {
        int fp = i >> 9, r = i & 511;
        int slot = fp >> 1, h = fp & 1;
        int k = 2*r + h;
        int pslot, pk_;
        if (b == 0) {
            pslot = slot;
            pk_ = slot ? (1023 - k) : ((1024 - k) & 1023);
        } else {
            pslot = 1 - slot;
            pk_ = 1023 - k;
        }
        float2 Zv = sb[fp*CH + r];
        float2 Zp = sb[(pslot*2 + (pk_ & 1))*CH + (pk_ >> 1)];
        float2 U  = make_float2(0.5f * (Zv.x + Zp.x),  0.5f * (Zv.y - Zp.y));
        float2 Kd = make_float2(0.5f * (Zv.y + Zp.y), -0.5f * (Zv.x - Zp.x));
        sa[fp*CH + r] = cmul(U, Kd);
    }
    __syncthreads();
    for (int i = t; i < 1024; i += TPB4) {
        int slot = i >> 9, kc = i & 511;
        int h = kc & 1, r0 = kc >> 1;
        int cb = (slot*2 + h)*CH;
        float2 S1 = sa[cb + r0];
        float2 S2 = sa[cb + r0 + 256];
        float2 E = make_float2(0.5f*(S1.x + S2.x), 0.5f*(S1.y + S2.y));
        float2 d = make_float2(0.5f*(S1.x - S2.x), 0.5f*(S1.y - S2.y));
        int kk = slot ? rowB : rowA;
        float2 o = cmul(twiddle_c(kk + (kc << 9), N2L, 1.0f), d);   // w^k * d
        sb[slot*CH + kc] = make_float2(E.x - o.y, E.y + o.x);       // E + i*O
    }
    __syncthreads();
    fft512q<+1>(sb, sa, t >> 7, t & 127, tw, t < 256);   // out sa chunks 0,1
    for (int i = t; i < 1024; i += TPB4) {
        int slot = i >> 9, m = i & 511;
        int kk = slot ? rowB : rowA;
        dB[kk * 512 + m] = cmul(sa[slot*CH + m],
                                twiddle_c((m*kk) & (L_SIZE-1), L_SIZE, 1.0f));
    }
}

// ---------------------------------------------------------------------------
// k5: column IFFT512 of the 512x512 matrix dB (2 cols/block, TPB=256,
//     grid=256). z2[p*512+m] = y[2n] + i y[2n+1], n = p*512+m, p < 256.
// ---------------------------------------------------------------------------
#define TPB5 256
__global__ void k5_inv_cols(const float* __restrict__ u, const float* __restrict__ Dp,
                            float* __restrict__ out) {
    __shared__ __align__(16) float2 sa[2*CH], sb[2*CH];
    __shared__ float2 tw[512];
    const int m0 = blockIdx.x * 2;
    const int t = threadIdx.x;
    for (int i = t; i < 512; i += TPB5) tw[i] = gtw512g[i];
    for (int i = t; i < 512; i += TPB5) {
        float4 x = *(const float4*)(dB + i * 512 + m0);
        sa[0*CH + i] = make_float2(x.x, x.y);
        sa[1*CH + i] = make_float2(x.z, x.w);
    }
    __syncthreads();
    fft512q<+1>(sa, sb, t >> 7, t & 127, tw, true);
    const float sc = 1.0f / (float)L_SIZE;
    const float Dv = Dp[0];
    for (int p = t; p < 256; p += TPB5) {
        float2 v0 = sb[0*CH + p];
        float2 v1 = sb[1*CH + p];
        int n2 = 2 * (p * 512 + m0);
        float4 uu = *(const float4*)(u + n2);
        float4 o;
        o.x = fmaf(Dv, uu.x, v0.x * sc);
        o.y = fmaf(Dv, uu.y, v0.y * sc);
        o.z = fmaf(Dv, uu.z, v1.x * sc);
        o.w = fmaf(Dv, uu.w, v1.y * sc);
        *(float4*)(out + n2) = o;
    }
}

// ---------------------------------------------------------------------------
extern "C" void kernel_launch(void* const* d_in, const int* in_sizes, int n_in,
                              void* d_out, int out_size) {
    (void)in_sizes; (void)n_in; (void)out_size;
    const float* u   = (const float*)d_in[0];
    const float* Lre = (const float*)d_in[1];
    const float* Lim = (const float*)d_in[2];
    const float* Pre = (const float*)d_in[3];
    const float* Pim = (const float*)d_in[4];
    const float* Bre = (const float*)d_in[5];
    const float* Bim = (const float*)d_in[6];
    const float* Cri = (const float*)d_in[7];
    const float* Dp  = (const float*)d_in[8];
    const float* ls  = (const float*)d_in[9];
    float* out = (float*)d_out;

    k0_gen      <<<1024, TPB0>>>(Lre, Lim, Pre, Pim, Bre, Bim, Cri, ls);
    k1_rowfft   <<<256,  TPB1>>>();
    k23_cols    <<<256,  TPB23>>>(u);
    k4_mega     <<<256,  TPB4>>>();
    k5_inv_cols <<<256,  TPB5>>>(u, Dp, out);
}

// round 15
// speedup vs baseline: 1.0404x; 1.0404x over previous
#include <cuda_runtime.h>

// S4 DPLR layer, round 15: same structure as round 14 (K real -> IFFT_L
// folded to L/2; generator+fold+row-FFT256 fused; 4 kernels) with
// __launch_bounds__ on every kernel — R14 failed launch because the fused
// 512-thread generator compiled to >128 regs/thread (64K regs/block cap).

#define L_SIZE   262144   // 2^18
#define N2L      524288   // 2^19
#define NHALF    131072   // 2^17 (folded IFFT_L length)
#define PI2      6.283185307179586f
#define CH       640      // smem chunk per 512-pt FFT (float2 units)
#define CH2      320      // smem chunk per 256-pt FFT (float2 units)

__device__ float4 dA4_[N2L/2];    // 4 MB scratch (float4-backed: 16B aligned)
__device__ float4 dB4_[N2L/2];    // 4 MB scratch
#define dA ((float2*)dA4_)
#define dB ((float2*)dB4_)
__device__ float2 gtw512g[512];    // exp(-2pi i k/512)
__device__ float2 gtw1024g[512];   // exp(-2pi i k/1024), k<512

typedef unsigned long long u64c;
#define NEG1P 0xBF800000BF800000ull   // packed (-1.0f, -1.0f)

static __device__ __forceinline__ u64c pk(float2 a) {
    u64c r; asm("mov.b64 %0, {%1, %2};" : "=l"(r) : "f"(a.x), "f"(a.y)); return r;
}
static __device__ __forceinline__ float2 upk(u64c a) {
    float2 r; asm("mov.b64 {%0, %1}, %2;" : "=f"(r.x), "=f"(r.y) : "l"(a)); return r;
}
static __device__ __forceinline__ u64c padd(u64c a, u64c b) {
    u64c r; asm("add.rn.f32x2 %0, %1, %2;" : "=l"(r) : "l"(a), "l"(b)); return r;
}
static __device__ __forceinline__ u64c pfma(u64c a, u64c b, u64c c) {
    u64c r; asm("fma.rn.f32x2 %0, %1, %2, %3;" : "=l"(r) : "l"(a), "l"(b), "l"(c)); return r;
}
static __device__ __forceinline__ u64c psub(u64c a, u64c b) {
    u64c r; asm("fma.rn.f32x2 %0, %1, %2, %3;" : "=l"(r) : "l"(b), "l"((u64c)NEG1P), "l"(a)); return r;
}

static __device__ __forceinline__ float2 cmul(float2 a, float2 b) {
    return make_float2(a.x*b.x - a.y*b.y, a.x*b.y + a.y*b.x);
}
static __device__ __forceinline__ float2 cadd(float2 a, float2 b) {
    return make_float2(a.x + b.x, a.y + b.y);
}
static __device__ __forceinline__ float2 csub(float2 a, float2 b) {
    return make_float2(a.x - b.x, a.y - b.y);
}

// exp(sgn * 2*pi*i * mm / n), mm in [0, n). Centered arg -> __sincosf safe.
static __device__ __forceinline__ float2 twiddle_c(int mm, int n, float sgn) {
    int tt = mm - ((mm >= (n >> 1)) ? n : 0);
    float ang = sgn * (PI2 / (float)n) * (float)tt;
    float s, c; __sincosf(ang, &s, &c);
    return make_float2(c, s);
}

template<int SIGN>
static __device__ __forceinline__ float2 twl(const float2* tw, int idx) {
    float2 w = tw[idx];
    if (SIGN > 0) w.y = -w.y;
    return w;
}
static __device__ __forceinline__ u64c pcmul(u64c a, float2 b) {
    float2 f = upk(a);
    return pk(cmul(f, b));
}
template<int SIGN>
static __device__ __forceinline__ u64c pmulpmi(u64c a) {   // *(-i) fwd, *(+i) inv
    float2 f = upk(a);
    return (SIGN < 0) ? pk(make_float2(f.y, -f.x)) : pk(make_float2(-f.y, f.x));
}

// radix-4 DIT butterfly in registers (packed complex), natural order.
template<int SIGN>
static __device__ __forceinline__ void r4p(u64c v[4]) {
    u64c t0 = padd(v[0], v[2]), t1 = psub(v[0], v[2]);
    u64c t2 = padd(v[1], v[3]), t3 = pmulpmi<SIGN>(psub(v[1], v[3]));
    v[0] = padd(t0, t2); v[2] = psub(t0, t2);
    v[1] = padd(t1, t3); v[3] = psub(t1, t3);
}

// Named barriers: 128-thread FFT group (fft512q), 64-thread group (fft256q).
static __device__ __forceinline__ void qbar(int f) {
    asm volatile("bar.sync %0, 128;" :: "r"(f + 1) : "memory");
}
static __device__ __forceinline__ void bar64(int f) {
    asm volatile("bar.sync %0, 64;" :: "r"(f + 1) : "memory");
}

// 512-pt FFT, 128 threads/FFT, 4 pts/thread (verified round-13).
// Natural input A[f*CH+0..511] -> natural output B[f*CH+0..511]; A clobbered.
// All block threads must call; `active` masks work. Caller syncs after fill.
template<int SIGN>
static __device__ __forceinline__ void fft512q(
    float2* A, float2* B, int f, int l, const float2* tw, bool active)
{
    const int ba = f * CH;
    u64c v[4];
    if (active) {       // stage 0: radix-2 over a (stride 256)
        #pragma unroll
        for (int h = 0; h < 2; ++h) {
            int np = l + 128*h;
            u64c x0 = pk(A[ba + np]), x1 = pk(A[ba + np + 256]);
            u64c F0 = padd(x0, x1), F1 = psub(x0, x1);
            F1 = pcmul(F1, twl<SIGN>(tw, np));            // W512^{n'}
            B[ba + np]       = upk(F0);
            B[ba + 256 + np] = upk(F1);
        }
    }
    qbar(f);
    {                   // stage 1: (j0 = l&1, m = l>>1), radix-4 over b
        const int j0 = l & 1, m = l >> 1;
        if (active) {
            #pragma unroll
            for (int b = 0; b < 4; ++b) v[b] = pk(B[ba + 256*j0 + 64*b + m]);
            r4p<SIGN>(v);
            #pragma unroll
            for (int j1 = 0; j1 < 4; ++j1) {
                if (j1) v[j1] = pcmul(v[j1], twl<SIGN>(tw, 2*m*j1));   // W256^{m j1}
                A[ba + 68*(j0 + 2*j1) + m] = upk(v[j1]);
            }
        }
    }
    qbar(f);
    {                   // stage 2: (G1 = l&7, m2 = l>>3), radix-4 over c
        const int G1 = l & 7, m2 = l >> 3;
        if (active) {
            #pragma unroll
            for (int c = 0; c < 4; ++c) v[c] = pk(A[ba + 68*G1 + 16*c + m2]);
            r4p<SIGN>(v);
            #pragma unroll
            for (int j2 = 0; j2 < 4; ++j2) {
                if (j2) v[j2] = pcmul(v[j2], twl<SIGN>(tw, 8*m2*j2));  // W64^{m2 j2}
                B[ba + 19*(G1 + 8*j2) + m2] = upk(v[j2]);
            }
        }
    }
    qbar(f);
    {                   // stage 3: (G2 = l&31, m3 = l>>5), radix-4 over d
        const int G2 = l & 31, m3 = l >> 5;
        if (active) {
            #pragma unroll
            for (int d = 0; d < 4; ++d) v[d] = pk(B[ba + 19*G2 + 4*d + m3]);
            r4p<SIGN>(v);
            #pragma unroll
            for (int j3 = 0; j3 < 4; ++j3) {
                if (j3) v[j3] = pcmul(v[j3], twl<SIGN>(tw, 32*m3*j3)); // W16^{m3 j3}
                A[ba + 5*(G2 + 32*j3) + m3] = upk(v[j3]);
            }
        }
    }
    qbar(f);
    if (active) {       // stage 4: l = G3, radix-4 over e -> j4
        #pragma unroll
        for (int e = 0; e < 4; ++e) v[e] = pk(A[ba + 5*l + e]);
        r4p<SIGN>(v);
        #pragma unroll
        for (int j4 = 0; j4 < 4; ++j4) B[ba + l + 128*j4] = upk(v[j4]);
    }
    __syncthreads();
}

// 256-pt FFT, 64 threads/FFT, 4 pts/thread, 4 radix-4 stages. Natural input
// X[f*CH2+0..255] -> natural output X[f*CH2+0..255] (Y scratch); digits
// n = 64a+16b+4c+d -> k = j0+4j1+16j2+64j3. All block threads must call.
template<int SIGN>
static __device__ __forceinline__ void fft256q(
    float2* X, float2* Y, int f, int l, const float2* tw, bool active)
{
    const int ba = f * CH2;
    u64c v[4];
    if (active) {       // stage 0: radix-4 over a; l = n' in [0,64)
        #pragma unroll
        for (int a = 0; a < 4; ++a) v[a] = pk(X[ba + l + 64*a]);
        r4p<SIGN>(v);
        #pragma unroll
        for (int j0 = 0; j0 < 4; ++j0) {
            if (j0) v[j0] = pcmul(v[j0], twl<SIGN>(tw, 2*l*j0));   // W256^{n' j0}
            Y[ba + 72*j0 + l] = upk(v[j0]);
        }
    }
    bar64(f);
    {                   // stage 1: (j0 = l&3, m = l>>2), radix-4 over b
        const int j0 = l & 3, m = l >> 2;
        if (active) {
            #pragma unroll
            for (int b = 0; b < 4; ++b) v[b] = pk(Y[ba + 72*j0 + m + 16*b]);
            r4p<SIGN>(v);
            #pragma unroll
            for (int j1 = 0; j1 < 4; ++j1) {
                if (j1) v[j1] = pcmul(v[j1], twl<SIGN>(tw, 8*m*j1));   // W64^{m j1}
                X[ba + 17*(j0 + 4*j1) + m] = upk(v[j1]);
            }
        }
    }
    bar64(f);
    {                   // stage 2: (G1 = l&15, m2 = l>>4), radix-4 over c
        const int G1 = l & 15, m2 = l >> 4;
        if (active) {
            #pragma unroll
            for (int c = 0; c < 4; ++c) v[c] = pk(X[ba + 17*G1 + m2 + 4*c]);
            r4p<SIGN>(v);
            #pragma unroll
            for (int j2 = 0; j2 < 4; ++j2) {
                if (j2) v[j2] = pcmul(v[j2], twl<SIGN>(tw, 32*m2*j2)); // W16^{m2 j2}
                Y[ba + 5*(G1 + 16*j2) + m2] = upk(v[j2]);
            }
        }
    }
    bar64(f);
    if (active) {       // stage 3: l = G2, radix-4 over d -> j3
        #pragma unroll
        for (int d = 0; d < 4; ++d) v[d] = pk(Y[ba + 5*l + d]);
        r4p<SIGN>(v);
        #pragma unroll
        for (int j3 = 0; j3 < 4; ++j3) X[ba + l + 64*j3] = upk(v[j3]);
    }
    __syncthreads();
}

// ---------------------------------------------------------------------------
// k01 FUSED: generator + Hermitian fold + T build + row IFFT256 + twiddle.
//   Block b holds rows (rowA = b, rowB = b?512-b:256) of atRoots A (512 each,
//   one root/thread/row). H = Hermitian part (K real => K = IFFT_L(H)).
//   T[kc] = (H[kc]+H[kc+256])/2 + i w^k (H[kc]-H[kc+256])/2, w=e^{+2pi i/L},
//   k = row + 512 kc. Row IFFT256 over kc + W_{L/2}^{c''*row} twiddle ->
//   dB[row*256 + c''] (512x256 half-size four-step intermediate).
//   grid=256, TPB=512, capped at 128 regs/thread via __launch_bounds__.
// ---------------------------------------------------------------------------
#define TPB01 512
__global__ void __launch_bounds__(TPB01, 1)
k01_gen(const float* __restrict__ Lre, const float* __restrict__ Lim,
        const float* __restrict__ Pre, const float* __restrict__ Pim,
        const float* __restrict__ Bre, const float* __restrict__ Bim,
        const float* __restrict__ Cri, const float* __restrict__ ls) {
    __shared__ float2 tw[512];
    __shared__ float  sLre[64], sLim[64];
    __shared__ u64c   sv[4][64], svs[4][64];
    __shared__ float2 rawA[512], rawB[512];
    __shared__ float2 fb0[2*CH2], fb1[2*CH2];
    const int t = threadIdx.x;
    const int b = blockIdx.x;

    // smem twiddle table (this kernel can't rely on globals being ready)
    if (t < 512) {
        float s, c; sincospif(-2.0f * (float)t / 512.0f, &s, &c);
        tw[t] = make_float2(c, s);
        if (b == 0) gtw512g[t] = make_float2(c, s);
        if (b == 1) {
            float s1, c1; sincospif(-2.0f * (float)t / 1024.0f, &s1, &c1);
            gtw1024g[t] = make_float2(c1, s1);
        }
    }
    if (t < 64) {
        float2 Pv = make_float2(Pre[t], Pim[t]);
        float2 Bv = make_float2(Bre[t], Bim[t]);
        float2 Cj = make_float2(Cri[2*t], -Cri[2*t+1]);   // conj(C)
        float2 Pj = make_float2(Pv.x, -Pv.y);             // conj(P) (Q = P)
        sLre[t] = Lre[t]; sLim[t] = Lim[t];
        float2 v0 = cmul(Cj, Bv), v1 = cmul(Cj, Pv);
        float2 v2 = cmul(Pj, Bv), v3 = cmul(Pj, Pv);
        sv[0][t] = pk(v0); svs[0][t] = pk(make_float2(v0.y, v0.x));
        sv[1][t] = pk(v1); svs[1][t] = pk(make_float2(v1.y, v1.x));
        sv[2][t] = pk(v2); svs[2][t] = pk(make_float2(v2.y, v2.x));
        sv[3][t] = pk(v3); svs[3][t] = pk(make_float2(v3.y, v3.x));
    }
    __syncthreads();

    const int rowA = b;
    const int rowB = (b == 0) ? 256 : 512 - b;
    const float step = expf(ls[0]);

    // generator: 2 roots/thread (rows rowA, rowB at column m = t).
    // sincosf Omega keeps 1+Omega != 0 at Nyquist (j = L/2 -> row 0, m=256).
    #pragma unroll 1
    for (int r = 0; r < 2; ++r) {
        const int row = r ? rowB : rowA;
        const int j   = row + (t << 9);
        float ang = -PI2 * ((float)j / (float)L_SIZE);
        float sn, cs; sincosf(ang, &sn, &cs);
        float2 onem = make_float2(1.f - cs, -sn);
        float2 onep = make_float2(1.f + cs,  sn);
        float invp = 1.f / (onep.x*onep.x + onep.y*onep.y);
        float2 cc = make_float2(2.f*onep.x*invp, -2.f*onep.y*invp);
        float2 qv = cmul(onem, make_float2(onep.x, -onep.y));
        float sfac = (2.f / step) * invp;
        float gx = qv.x * sfac, gy = qv.y * sfac;

        const float S = 5.9604644775390625e-8f;    // 2^-24 (overflow-free pairing)
        u64c a00 = 0ull, a01 = 0ull, a10 = 0ull, a11 = 0ull;
        #pragma unroll 8
        for (int q = 0; q < 32; ++q) {
            const int n = 2*q;
            float dx0 = gx - sLre[n],   dy0 = gy - sLim[n];
            float dx1 = gx - sLre[n+1], dy1 = gy - sLim[n+1];
            float b0 = fmaf(dx0, dx0, dy0*dy0) * S;
            float b1 = fmaf(dx1, dx1, dy1*dy1) * S;
            float tq = 1.f / (b0 * b1);
            float i0 = b1 * tq * S;
            float i1 = b0 * tq * S;
            float rx0 = dx0*i0, p0 = dy0*i0;
            float rx1 = dx1*i1, p1 = dy1*i1;
            u64c pa0 = pk(make_float2(rx0,  rx0));
            u64c pb0 = pk(make_float2(p0,  -p0));
            u64c pa1 = pk(make_float2(rx1,  rx1));
            u64c pb1 = pk(make_float2(p1,  -p1));
            a00 = pfma(pa0, sv[0][n], pfma(pb0, svs[0][n], a00));
            a01 = pfma(pa0, sv[1][n], pfma(pb0, svs[1][n], a01));
            a10 = pfma(pa0, sv[2][n], pfma(pb0, svs[2][n], a10));
            a11 = pfma(pa0, sv[3][n], pfma(pb0, svs[3][n], a11));
            a00 = pfma(pa1, sv[0][n+1], pfma(pb1, svs[0][n+1], a00));
            a01 = pfma(pa1, sv[1][n+1], pfma(pb1, svs[1][n+1], a01));
            a10 = pfma(pa1, sv[2][n+1], pfma(pb1, svs[2][n+1], a10));
            a11 = pfma(pa1, sv[3][n+1], pfma(pb1, svs[3][n+1], a11));
        }
        float2 k00 = upk(a00), k01 = upk(a01), k10 = upk(a10), k11 = upk(a11);
        float2 den = make_float2(1.f + k11.x, k11.y);
        float invd = 1.f / (den.x*den.x + den.y*den.y);
        float2 num = cmul(k01, k10);
        float2 tq2 = cmul(num, make_float2(den.x*invd, -den.y*invd));
        float2 at  = cmul(cc, make_float2(k00.x - tq2.x, k00.y - tq2.y));
        if (r) rawB[t] = at; else rawA[t] = at;
    }
    __syncthreads();

    // H + T: thread i -> (row f = i>>8, kc = i&255). T into fb0 chunk f.
    {
        const int f  = t >> 8;       // 0: rowA, 1: rowB
        const int kc = t & 255;
        const int row = f ? rowB : rowA;
        float2 H1, H2;
        #pragma unroll
        for (int s = 0; s < 2; ++s) {
            int m = kc + 256*s;
            float2 a, p;
            if (f == 0) {
                a = rawA[m];
                p = (b == 0) ? rawA[(512 - m) & 511] : rawB[511 - m];
            } else {
                a = rawB[m];
                p = (b == 0) ? rawB[511 - m]          : rawA[511 - m];
            }
            float2 h = make_float2(0.5f*(a.x + p.x), 0.5f*(a.y - p.y));
            if (s) H2 = h; else H1 = h;
        }
        float2 E = make_float2(0.5f*(H1.x + H2.x), 0.5f*(H1.y + H2.y));
        float2 d = make_float2(0.5f*(H1.x - H2.x), 0.5f*(H1.y - H2.y));
        float2 w = twiddle_c((row + (kc << 9)) & (L_SIZE - 1), L_SIZE, 1.0f);
        float2 o = cmul(w, d);
        fb0[f*CH2 + kc] = make_float2(E.x - o.y, E.y + o.x);   // E + i*(w*d)
    }
    __syncthreads();

    // 2 row IFFT256s (threads t<128; f = t>>6, l = t&63)
    fft256q<+1>(fb0, fb1, t >> 6, t & 63, tw, t < 128);

    // inter-pass twiddle for the L/2 four-step + store (coalesced)
    {
        const int f = t >> 8, cc2 = t & 255;
        const int row = f ? rowB : rowA;
        float2 val = fb0[f*CH2 + cc2];
        dB[row * 256 + cc2] =
            cmul(val, twiddle_c((row * cc2) & (NHALF - 1), NHALF, 1.0f));
    }
}

// ---------------------------------------------------------------------------
// k23: block bid -> half-size column c'' = bid; phase A: ONE column IFFT512
//   over rows of dB -> z2; K[2n'] = Re z2[n'], K[2n'+1] = Im, scale 2/L.
//   Phase B: z = u + i*K for the 4 z-columns {2bid, 2bid+1, 2bid+512,
//   2bid+513}; 4 fwd FFT512 + fwd twiddle -> dA[k1*1024 + c].
//   grid=256, TPB=512.
// ---------------------------------------------------------------------------
#define TPB23 512
__global__ void __launch_bounds__(TPB23, 1)
k23_cols(const float* __restrict__ u) {
    __shared__ __align__(16) float2 sa[4*CH], sb[4*CH];
    __shared__ float2 tw[512];
    __shared__ float su[4*260];
    const int bid = blockIdx.x;
    const int m0  = 2 * bid;
    const int t = threadIdx.x;
    for (int i = t; i < 512; i += TPB23) tw[i] = gtw512g[i];
    // phase A load: one column of the 512x256 matrix dB
    for (int i = t; i < 512; i += TPB23)
        sa[i] = dB[i * 256 + bid];
    __syncthreads();
    if (t >= 128) {   // prefetch u during phase A
        for (int i = t - 128; i < 1024; i += 384) {
            int fp = i & 3, rr = i >> 2;
            int c = m0 + (fp & 1) + (fp >> 1) * 512;
            su[fp * 260 + rr] = u[rr * 1024 + c];
        }
    }
    fft512q<+1>(sa, sb, t >> 7, t & 127, tw, t < 128);
    // build z: K[rr*1024 + c] = (f? Im : Re) zc[2rr+half] * (2/L)
    const float sc = 1.0f / (float)NHALF;    // 2/L
    for (int i = t; i < 2048; i += TPB23) {
        int fp = i >> 9, rr = i & 511;
        int half = fp >> 1, f = fp & 1;
        float2 z = make_float2(0.f, 0.f);
        if (rr < 256) {
            float2 zc = sb[2*rr + half];
            float kv = (f ? zc.y : zc.x) * sc;
            z = make_float2(su[fp * 260 + rr], kv);
        }
        sa[fp*CH + rr] = z;
    }
    __syncthreads();
    fft512q<-1>(sa, sb, t >> 7, t & 127, tw, true);
    for (int i = t; i < 2048; i += TPB23) {
        int fp = i & 3, k1 = i >> 2;
        int half = fp >> 1, f = fp & 1;
        int c = m0 + f + half * 512;
        int mm = (c * k1) & (N2L - 1);
        dA[k1 * 1024 + c] = cmul(sb[fp*CH + k1], twiddle_c(mm, N2L, -1.0f));
    }
}

// ---------------------------------------------------------------------------
// k4: (identical to verified round-13) paired rows (k1, 512-k1); fwd FFT1024
//   x2 via radix-2 split; Hermitian pointwise S = U*Kd; REAL-OUTPUT fold to
//   one FFT512 per slot + W_L twiddle -> dB[k1*512 + m]. grid=256, TPB=512.
// ---------------------------------------------------------------------------
#define TPB4 512
__global__ void __launch_bounds__(TPB4, 1)
k4_mega() {
    __shared__ __align__(16) float2 sa[4*CH], sb[4*CH];
    __shared__ float2 tw[512], twh[512];
    const int t = threadIdx.x;
    for (int i = t; i < 512; i += TPB4) { tw[i] = gtw512g[i]; twh[i] = gtw1024g[i]; }
    const int b = blockIdx.x;
    const int rowA = b;
    const int rowB = (b == 0) ? 256 : 512 - b;

    for (int i = t; i < 1024; i += TPB4) {
        int slot = i >> 9, m2 = i & 511;
        int row = slot ? rowB : rowA;
        float4 x = ((const float4*)(dA + row * 1024))[m2];
        *(float4*)&sb[slot * 1024 + 2*m2] = x;
    }
    __syncthreads();
    for (int i = t; i < 1024; i += TPB4) {
        int slot = i >> 9, m = i & 511;
        float2 a = sb[slot * 1024 + m];
        float2 c = sb[slot * 1024 + m + 512];
        sa[(slot*2 + 0)*CH + m] = cadd(a, c);
        sa[(slot*2 + 1)*CH + m] = cmul(csub(a, c), twh[m]);
    }
    __syncthreads();
    fft512q<-1>(sa, sb, t >> 7, t & 127, tw, true);
    for (int i = t; i < 2048; i += TPB4) {
        int fp = i >> 9, r = i & 511;
        int slot = fp >> 1, h = fp & 1;
        int k = 2*r + h;
        int pslot, pk_;
        if (b == 0) {
            pslot = slot;
            pk_ = slot ? (1023 - k) : ((1024 - k) & 1023);
        } else {
            pslot = 1 - slot;
            pk_ = 1023 - k;
        }
        float2 Zv = sb[fp*CH + r];
        float2 Zp = sb[(pslot*2 + (pk_ & 1))*CH + (pk_ >> 1)];
        float2 U  = make_float2(0.5f * (Zv.x + Zp.x),  0.5f * (Zv.y - Zp.y));
        float2 Kd = make_float2(0.5f * (Zv.y + Zp.y), -0.5f * (Zv.x - Zp.x));
        sa[fp*CH + r] = cmul(U, Kd);
    }
    __syncthreads();
    for (int i = t; i < 1024; i += TPB4) {
        int slot = i >> 9, kc = i & 511;
        int h = kc & 1, r0 = kc >> 1;
        int cb = (slot*2 + h)*CH;
        float2 S1 = sa[cb + r0];
        float2 S2 = sa[cb + r0 + 256];
        float2 E = make_float2(0.5f*(S1.x + S2.x), 0.5f*(S1.y + S2.y));
        float2 d = make_float2(0.5f*(S1.x - S2.x), 0.5f*(S1.y - S2.y));
        int kk = slot ? rowB : rowA;
        float2 o = cmul(twiddle_c(kk + (kc << 9), N2L, 1.0f), d);   // w^k * d
        sb[slot*CH + kc] = make_float2(E.x - o.y, E.y + o.x);       // E + i*O
    }
    __syncthreads();
    fft512q<+1>(sb, sa, t >> 7, t & 127, tw, t < 256);   // out sa chunks 0,1
    for (int i = t; i < 1024; i += TPB4) {
        int slot = i >> 9, m = i & 511;
        int kk = slot ? rowB : rowA;
        dB[kk * 512 + m] = cmul(sa[slot*CH + m],
                                twiddle_c((m*kk) & (L_SIZE-1), L_SIZE, 1.0f));
    }
}

// ---------------------------------------------------------------------------
// k5: (identical to verified round-13) column IFFT512 of dB (512x512);
//   z2[p*512+m] = y[2n] + i y[2n+1], n = p*512+m, p < 256. grid=256, TPB=256.
// ---------------------------------------------------------------------------
#define TPB5 256
__global__ void __launch_bounds__(TPB5, 2)
k5_inv_cols(const float* __restrict__ u, const float* __restrict__ Dp,
            float* __restrict__ out) {
    __shared__ __align__(16) float2 sa[2*CH], sb[2*CH];
    __shared__ float2 tw[512];
    const int m0 = blockIdx.x * 2;
    const int t = threadIdx.x;
    for (int i = t; i < 512; i += TPB5) tw[i] = gtw512g[i];
    for (int i = t; i < 512; i += TPB5) {
        float4 x = *(const float4*)(dB + i * 512 + m0);
        sa[0*CH + i] = make_float2(x.x, x.y);
        sa[1*CH + i] = make_float2(x.z, x.w);
    }
    __syncthreads();
    fft512q<+1>(sa, sb, t >> 7, t & 127, tw, true);
    const float sc = 1.0f / (float)L_SIZE;
    const float Dv = Dp[0];
    for (int p = t; p < 256; p += TPB5) {
        float2 v0 = sb[0*CH + p];
        float2 v1 = sb[1*CH + p];
        int n2 = 2 * (p * 512 + m0);
        float4 uu = *(const float4*)(u + n2);
        float4 o;
        o.x = fmaf(Dv, uu.x, v0.x * sc);
        o.y = fmaf(Dv, uu.y, v0.y * sc);
        o.z = fmaf(Dv, uu.z, v1.x * sc);
        o.w = fmaf(Dv, uu.w, v1.y * sc);
        *(float4*)(out + n2) = o;
    }
}

// ---------------------------------------------------------------------------
extern "C" void kernel_launch(void* const* d_in, const int* in_sizes, int n_in,
                              void* d_out, int out_size) {
    (void)in_sizes; (void)n_in; (void)out_size;
    const float* u   = (const float*)d_in[0];
    const float* Lre = (const float*)d_in[1];
    const float* Lim = (const float*)d_in[2];
    const float* Pre = (const float*)d_in[3];
    const float* Pim = (const float*)d_in[4];
    const float* Bre = (const float*)d_in[5];
    const float* Bim = (const float*)d_in[6];
    const float* Cri = (const float*)d_in[7];
    const float* Dp  = (const float*)d_in[8];
    const float* ls  = (const float*)d_in[9];
    float* out = (float*)d_out;

    k01_gen     <<<256, TPB01>>>(Lre, Lim, Pre, Pim, Bre, Bim, Cri, ls);
    k23_cols    <<<256, TPB23>>>(u);
    k4_mega     <<<256, TPB4>>>();
    k5_inv_cols <<<256, TPB5>>>(u, Dp, out);
}

// round 16
// speedup vs baseline: 1.0464x; 1.0058x over previous
#include <cuda_runtime.h>

// S4 DPLR layer, round 16: producer-side layout fixes for the two column
// gathers that dominated R15's profile. k4 stores dB pair-tiled so k5's
// column-pair read is one contiguous 8KB block; k01 stores its half-size
// matrix transposed so k23's column read is a contiguous 4KB row. k23's dA
// store vectorized to float4. Everything else identical to round 15.

#define L_SIZE   262144   // 2^18
#define N2L      524288   // 2^19
#define NHALF    131072   // 2^17 (folded IFFT_L length)
#define PI2      6.283185307179586f
#define CH       640      // smem chunk per 512-pt FFT (float2 units)
#define CH2      320      // smem chunk per 256-pt FFT (float2 units)

__device__ float4 dA4_[N2L/2];    // 4 MB scratch (float4-backed: 16B aligned)
__device__ float4 dB4_[N2L/2];    // 4 MB scratch
#define dA ((float2*)dA4_)
#define dB ((float2*)dB4_)
__device__ float2 gtw512g[512];    // exp(-2pi i k/512)
__device__ float2 gtw1024g[512];   // exp(-2pi i k/1024), k<512

typedef unsigned long long u64c;
#define NEG1P 0xBF800000BF800000ull   // packed (-1.0f, -1.0f)

static __device__ __forceinline__ u64c pk(float2 a) {
    u64c r; asm("mov.b64 %0, {%1, %2};" : "=l"(r) : "f"(a.x), "f"(a.y)); return r;
}
static __device__ __forceinline__ float2 upk(u64c a) {
    float2 r; asm("mov.b64 {%0, %1}, %2;" : "=f"(r.x), "=f"(r.y) : "l"(a)); return r;
}
static __device__ __forceinline__ u64c padd(u64c a, u64c b) {
    u64c r; asm("add.rn.f32x2 %0, %1, %2;" : "=l"(r) : "l"(a), "l"(b)); return r;
}
static __device__ __forceinline__ u64c pfma(u64c a, u64c b, u64c c) {
    u64c r; asm("fma.rn.f32x2 %0, %1, %2, %3;" : "=l"(r) : "l"(a), "l"(b), "l"(c)); return r;
}
static __device__ __forceinline__ u64c psub(u64c a, u64c b) {
    u64c r; asm("fma.rn.f32x2 %0, %1, %2, %3;" : "=l"(r) : "l"(b), "l"((u64c)NEG1P), "l"(a)); return r;
}

static __device__ __forceinline__ float2 cmul(float2 a, float2 b) {
    return make_float2(a.x*b.x - a.y*b.y, a.x*b.y + a.y*b.x);
}
static __device__ __forceinline__ float2 cadd(float2 a, float2 b) {
    return make_float2(a.x + b.x, a.y + b.y);
}
static __device__ __forceinline__ float2 csub(float2 a, float2 b) {
    return make_float2(a.x - b.x, a.y - b.y);
}

// exp(sgn * 2*pi*i * mm / n), mm in [0, n). Centered arg -> __sincosf safe.
static __device__ __forceinline__ float2 twiddle_c(int mm, int n, float sgn) {
    int tt = mm - ((mm >= (n >> 1)) ? n : 0);
    float ang = sgn * (PI2 / (float)n) * (float)tt;
    float s, c; __sincosf(ang, &s, &c);
    return make_float2(c, s);
}

template<int SIGN>
static __device__ __forceinline__ float2 twl(const float2* tw, int idx) {
    float2 w = tw[idx];
    if (SIGN > 0) w.y = -w.y;
    return w;
}
static __device__ __forceinline__ u64c pcmul(u64c a, float2 b) {
    float2 f = upk(a);
    return pk(cmul(f, b));
}
template<int SIGN>
static __device__ __forceinline__ u64c pmulpmi(u64c a) {   // *(-i) fwd, *(+i) inv
    float2 f = upk(a);
    return (SIGN < 0) ? pk(make_float2(f.y, -f.x)) : pk(make_float2(-f.y, f.x));
}

// radix-4 DIT butterfly in registers (packed complex), natural order.
template<int SIGN>
static __device__ __forceinline__ void r4p(u64c v[4]) {
    u64c t0 = padd(v[0], v[2]), t1 = psub(v[0], v[2]);
    u64c t2 = padd(v[1], v[3]), t3 = pmulpmi<SIGN>(psub(v[1], v[3]));
    v[0] = padd(t0, t2); v[2] = psub(t0, t2);
    v[1] = padd(t1, t3); v[3] = psub(t1, t3);
}

// Named barriers: 128-thread FFT group (fft512q), 64-thread group (fft256q).
static __device__ __forceinline__ void qbar(int f) {
    asm volatile("bar.sync %0, 128;" :: "r"(f + 1) : "memory");
}
static __device__ __forceinline__ void bar64(int f) {
    asm volatile("bar.sync %0, 64;" :: "r"(f + 1) : "memory");
}

// 512-pt FFT, 128 threads/FFT, 4 pts/thread (verified round-13).
// Natural input A[f*CH+0..511] -> natural output B[f*CH+0..511]; A clobbered.
// All block threads must call; `active` masks work. Caller syncs after fill.
template<int SIGN>
static __device__ __forceinline__ void fft512q(
    float2* A, float2* B, int f, int l, const float2* tw, bool active)
{
    const int ba = f * CH;
    u64c v[4];
    if (active) {       // stage 0: radix-2 over a (stride 256)
        #pragma unroll
        for (int h = 0; h < 2; ++h) {
            int np = l + 128*h;
            u64c x0 = pk(A[ba + np]), x1 = pk(A[ba + np + 256]);
            u64c F0 = padd(x0, x1), F1 = psub(x0, x1);
            F1 = pcmul(F1, twl<SIGN>(tw, np));            // W512^{n'}
            B[ba + np]       = upk(F0);
            B[ba + 256 + np] = upk(F1);
        }
    }
    qbar(f);
    {                   // stage 1: (j0 = l&1, m = l>>1), radix-4 over b
        const int j0 = l & 1, m = l >> 1;
        if (active) {
            #pragma unroll
            for (int b = 0; b < 4; ++b) v[b] = pk(B[ba + 256*j0 + 64*b + m]);
            r4p<SIGN>(v);
            #pragma unroll
            for (int j1 = 0; j1 < 4; ++j1) {
                if (j1) v[j1] = pcmul(v[j1], twl<SIGN>(tw, 2*m*j1));   // W256^{m j1}
                A[ba + 68*(j0 + 2*j1) + m] = upk(v[j1]);
            }
        }
    }
    qbar(f);
    {                   // stage 2: (G1 = l&7, m2 = l>>3), radix-4 over c
        const int G1 = l & 7, m2 = l >> 3;
        if (active) {
            #pragma unroll
            for (int c = 0; c < 4; ++c) v[c] = pk(A[ba + 68*G1 + 16*c + m2]);
            r4p<SIGN>(v);
            #pragma unroll
            for (int j2 = 0; j2 < 4; ++j2) {
                if (j2) v[j2] = pcmul(v[j2], twl<SIGN>(tw, 8*m2*j2));  // W64^{m2 j2}
                B[ba + 19*(G1 + 8*j2) + m2] = upk(v[j2]);
            }
        }
    }
    qbar(f);
    {                   // stage 3: (G2 = l&31, m3 = l>>5), radix-4 over d
        const int G2 = l & 31, m3 = l >> 5;
        if (active) {
            #pragma unroll
            for (int d = 0; d < 4; ++d) v[d] = pk(B[ba + 19*G2 + 4*d + m3]);
            r4p<SIGN>(v);
            #pragma unroll
            for (int j3 = 0; j3 < 4; ++j3) {
                if (j3) v[j3] = pcmul(v[j3], twl<SIGN>(tw, 32*m3*j3)); // W16^{m3 j3}
                A[ba + 5*(G2 + 32*j3) + m3] = upk(v[j3]);
            }
        }
    }
    qbar(f);
    if (active) {       // stage 4: l = G3, radix-4 over e -> j4
        #pragma unroll
        for (int e = 0; e < 4; ++e) v[e] = pk(A[ba + 5*l + e]);
        r4p<SIGN>(v);
        #pragma unroll
        for (int j4 = 0; j4 < 4; ++j4) B[ba + l + 128*j4] = upk(v[j4]);
    }
    __syncthreads();
}

// 256-pt FFT, 64 threads/FFT, 4 pts/thread, 4 radix-4 stages. Natural input
// X[f*CH2+0..255] -> natural output X[f*CH2+0..255] (Y scratch).
template<int SIGN>
static __device__ __forceinline__ void fft256q(
    float2* X, float2* Y, int f, int l, const float2* tw, bool active)
{
    const int ba = f * CH2;
    u64c v[4];
    if (active) {       // stage 0: radix-4 over a; l = n' in [0,64)
        #pragma unroll
        for (int a = 0; a < 4; ++a) v[a] = pk(X[ba + l + 64*a]);
        r4p<SIGN>(v);
        #pragma unroll
        for (int j0 = 0; j0 < 4; ++j0) {
            if (j0) v[j0] = pcmul(v[j0], twl<SIGN>(tw, 2*l*j0));   // W256^{n' j0}
            Y[ba + 72*j0 + l] = upk(v[j0]);
        }
    }
    bar64(f);
    {                   // stage 1: (j0 = l&3, m = l>>2), radix-4 over b
        const int j0 = l & 3, m = l >> 2;
        if (active) {
            #pragma unroll
            for (int b = 0; b < 4; ++b) v[b] = pk(Y[ba + 72*j0 + m + 16*b]);
            r4p<SIGN>(v);
            #pragma unroll
            for (int j1 = 0; j1 < 4; ++j1) {
                if (j1) v[j1] = pcmul(v[j1], twl<SIGN>(tw, 8*m*j1));   // W64^{m j1}
                X[ba + 17*(j0 + 4*j1) + m] = upk(v[j1]);
            }
        }
    }
    bar64(f);
    {                   // stage 2: (G1 = l&15, m2 = l>>4), radix-4 over c
        const int G1 = l & 15, m2 = l >> 4;
        if (active) {
            #pragma unroll
            for (int c = 0; c < 4; ++c) v[c] = pk(X[ba + 17*G1 + m2 + 4*c]);
            r4p<SIGN>(v);
            #pragma unroll
            for (int j2 = 0; j2 < 4; ++j2) {
                if (j2) v[j2] = pcmul(v[j2], twl<SIGN>(tw, 32*m2*j2)); // W16^{m2 j2}
                Y[ba + 5*(G1 + 16*j2) + m2] = upk(v[j2]);
            }
        }
    }
    bar64(f);
    if (active) {       // stage 3: l = G2, radix-4 over d -> j3
        #pragma unroll
        for (int d = 0; d < 4; ++d) v[d] = pk(Y[ba + 5*l + d]);
        r4p<SIGN>(v);
        #pragma unroll
        for (int j3 = 0; j3 < 4; ++j3) X[ba + l + 64*j3] = upk(v[j3]);
    }
    __syncthreads();
}

// ---------------------------------------------------------------------------
// k01 FUSED: generator + Hermitian fold + T build + row IFFT256 + twiddle.
//   STORE TRANSPOSED: dB[c''*512 + row] so k23's column read is contiguous.
//   grid=256, TPB=512.
// ---------------------------------------------------------------------------
#define TPB01 512
__global__ void __launch_bounds__(TPB01, 1)
k01_gen(const float* __restrict__ Lre, const float* __restrict__ Lim,
        const float* __restrict__ Pre, const float* __restrict__ Pim,
        const float* __restrict__ Bre, const float* __restrict__ Bim,
        const float* __restrict__ Cri, const float* __restrict__ ls) {
    __shared__ float2 tw[512];
    __shared__ float  sLre[64], sLim[64];
    __shared__ u64c   sv[4][64], svs[4][64];
    __shared__ float2 rawA[512], rawB[512];
    __shared__ float2 fb0[2*CH2], fb1[2*CH2];
    const int t = threadIdx.x;
    const int b = blockIdx.x;

    if (t < 512) {
        float s, c; sincospif(-2.0f * (float)t / 512.0f, &s, &c);
        tw[t] = make_float2(c, s);
        if (b == 0) gtw512g[t] = make_float2(c, s);
        if (b == 1) {
            float s1, c1; sincospif(-2.0f * (float)t / 1024.0f, &s1, &c1);
            gtw1024g[t] = make_float2(c1, s1);
        }
    }
    if (t < 64) {
        float2 Pv = make_float2(Pre[t], Pim[t]);
        float2 Bv = make_float2(Bre[t], Bim[t]);
        float2 Cj = make_float2(Cri[2*t], -Cri[2*t+1]);   // conj(C)
        float2 Pj = make_float2(Pv.x, -Pv.y);             // conj(P) (Q = P)
        sLre[t] = Lre[t]; sLim[t] = Lim[t];
        float2 v0 = cmul(Cj, Bv), v1 = cmul(Cj, Pv);
        float2 v2 = cmul(Pj, Bv), v3 = cmul(Pj, Pv);
        sv[0][t] = pk(v0); svs[0][t] = pk(make_float2(v0.y, v0.x));
        sv[1][t] = pk(v1); svs[1][t] = pk(make_float2(v1.y, v1.x));
        sv[2][t] = pk(v2); svs[2][t] = pk(make_float2(v2.y, v2.x));
        sv[3][t] = pk(v3); svs[3][t] = pk(make_float2(v3.y, v3.x));
    }
    __syncthreads();

    const int rowA = b;
    const int rowB = (b == 0) ? 256 : 512 - b;
    const float step = expf(ls[0]);

    #pragma unroll 1
    for (int r = 0; r < 2; ++r) {
        const int row = r ? rowB : rowA;
        const int j   = row + (t << 9);
        float ang = -PI2 * ((float)j / (float)L_SIZE);
        float sn, cs; sincosf(ang, &sn, &cs);   // Nyquist-safe Omega
        float2 onem = make_float2(1.f - cs, -sn);
        float2 onep = make_float2(1.f + cs,  sn);
        float invp = 1.f / (onep.x*onep.x + onep.y*onep.y);
        float2 cc = make_float2(2.f*onep.x*invp, -2.f*onep.y*invp);
        float2 qv = cmul(onem, make_float2(onep.x, -onep.y));
        float sfac = (2.f / step) * invp;
        float gx = qv.x * sfac, gy = qv.y * sfac;

        const float S = 5.9604644775390625e-8f;    // 2^-24
        u64c a00 = 0ull, a01 = 0ull, a10 = 0ull, a11 = 0ull;
        #pragma unroll 8
        for (int q = 0; q < 32; ++q) {
            const int n = 2*q;
            float dx0 = gx - sLre[n],   dy0 = gy - sLim[n];
            float dx1 = gx - sLre[n+1], dy1 = gy - sLim[n+1];
            float b0 = fmaf(dx0, dx0, dy0*dy0) * S;
            float b1 = fmaf(dx1, dx1, dy1*dy1) * S;
            float tq = 1.f / (b0 * b1);
            float i0 = b1 * tq * S;
            float i1 = b0 * tq * S;
            float rx0 = dx0*i0, p0 = dy0*i0;
            float rx1 = dx1*i1, p1 = dy1*i1;
            u64c pa0 = pk(make_float2(rx0,  rx0));
            u64c pb0 = pk(make_float2(p0,  -p0));
            u64c pa1 = pk(make_float2(rx1,  rx1));
            u64c pb1 = pk(make_float2(p1,  -p1));
            a00 = pfma(pa0, sv[0][n], pfma(pb0, svs[0][n], a00));
            a01 = pfma(pa0, sv[1][n], pfma(pb0, svs[1][n], a01));
            a10 = pfma(pa0, sv[2][n], pfma(pb0, svs[2][n], a10));
            a11 = pfma(pa0, sv[3][n], pfma(pb0, svs[3][n], a11));
            a00 = pfma(pa1, sv[0][n+1], pfma(pb1, svs[0][n+1], a00));
            a01 = pfma(pa1, sv[1][n+1], pfma(pb1, svs[1][n+1], a01));
            a10 = pfma(pa1, sv[2][n+1], pfma(pb1, svs[2][n+1], a10));
            a11 = pfma(pa1, sv[3][n+1], pfma(pb1, svs[3][n+1], a11));
        }
        float2 k00 = upk(a00), k01 = upk(a01), k10 = upk(a10), k11 = upk(a11);
        float2 den = make_float2(1.f + k11.x, k11.y);
        float invd = 1.f / (den.x*den.x + den.y*den.y);
        float2 num = cmul(k01, k10);
        float2 tq2 = cmul(num, make_float2(den.x*invd, -den.y*invd));
        float2 at  = cmul(cc, make_float2(k00.x - tq2.x, k00.y - tq2.y));
        if (r) rawB[t] = at; else rawA[t] = at;
    }
    __syncthreads();

    // H + T: thread i -> (row f = i>>8, kc = i&255). T into fb0 chunk f.
    {
        const int f  = t >> 8;       // 0: rowA, 1: rowB
        const int kc = t & 255;
        const int row = f ? rowB : rowA;
        float2 H1, H2;
        #pragma unroll
        for (int s = 0; s < 2; ++s) {
            int m = kc + 256*s;
            float2 a, p;
            if (f == 0) {
                a = rawA[m];
                p = (b == 0) ? rawA[(512 - m) & 511] : rawB[511 - m];
            } else {
                a = rawB[m];
                p = (b == 0) ? rawB[511 - m]          : rawA[511 - m];
            }
            float2 h = make_float2(0.5f*(a.x + p.x), 0.5f*(a.y - p.y));
            if (s) H2 = h; else H1 = h;
        }
        float2 E = make_float2(0.5f*(H1.x + H2.x), 0.5f*(H1.y + H2.y));
        float2 d = make_float2(0.5f*(H1.x - H2.x), 0.5f*(H1.y - H2.y));
        float2 w = twiddle_c((row + (kc << 9)) & (L_SIZE - 1), L_SIZE, 1.0f);
        float2 o = cmul(w, d);
        fb0[f*CH2 + kc] = make_float2(E.x - o.y, E.y + o.x);   // E + i*(w*d)
    }
    __syncthreads();

    // 2 row IFFT256s (threads t<128; f = t>>6, l = t&63)
    fft256q<+1>(fb0, fb1, t >> 6, t & 63, tw, t < 128);

    // inter-pass twiddle + TRANSPOSED store: dB[c''*512 + row]
    {
        const int f = t >> 8, cc2 = t & 255;
        const int row = f ? rowB : rowA;
        float2 val = fb0[f*CH2 + cc2];
        dB[cc2 * 512 + row] =
            cmul(val, twiddle_c((row * cc2) & (NHALF - 1), NHALF, 1.0f));
    }
}

// ---------------------------------------------------------------------------
// k23: block bid -> half-size column c'' = bid. Phase A load is now a
//   CONTIGUOUS 4KB row read (dB transposed by k01). Phase B: z = u + i*K for
//   z-columns {2bid, 2bid+1, 2bid+512, 2bid+513}; 4 fwd FFT512 + fwd twiddle
//   -> dA[k1*1024 + c] with float4 pair stores. grid=256, TPB=512.
// ---------------------------------------------------------------------------
#define TPB23 512
__global__ void __launch_bounds__(TPB23, 1)
k23_cols(const float* __restrict__ u) {
    __shared__ __align__(16) float2 sa[4*CH], sb[4*CH];
    __shared__ float2 tw[512];
    __shared__ float su[4*260];
    const int bid = blockIdx.x;
    const int m0  = 2 * bid;
    const int t = threadIdx.x;
    for (int i = t; i < 512; i += TPB23) tw[i] = gtw512g[i];
    // phase A load: contiguous row of the transposed 256x512 matrix
    for (int i = t; i < 512; i += TPB23)
        sa[i] = dB[bid * 512 + i];
    __syncthreads();
    if (t >= 128) {   // prefetch u during phase A
        for (int i = t - 128; i < 1024; i += 384) {
            int fp = i & 3, rr = i >> 2;
            int c = m0 + (fp & 1) + (fp >> 1) * 512;
            su[fp * 260 + rr] = u[rr * 1024 + c];
        }
    }
    fft512q<+1>(sa, sb, t >> 7, t & 127, tw, t < 128);
    // build z: K[rr*1024 + c] = (f? Im : Re) zc[2rr+half] * (2/L)
    const float sc = 1.0f / (float)NHALF;    // 2/L
    for (int i = t; i < 2048; i += TPB23) {
        int fp = i >> 9, rr = i & 511;
        int half = fp >> 1, f = fp & 1;
        float2 z = make_float2(0.f, 0.f);
        if (rr < 256) {
            float2 zc = sb[2*rr + half];
            float kv = (f ? zc.y : zc.x) * sc;
            z = make_float2(su[fp * 260 + rr], kv);
        }
        sa[fp*CH + rr] = z;
    }
    __syncthreads();
    fft512q<-1>(sa, sb, t >> 7, t & 127, tw, true);
    for (int i = t; i < 1024; i += TPB23) {
        int half = i >> 9, k1 = i & 511;
        int c0 = m0 + half * 512;
        float2 ya = cmul(sb[(2*half    )*CH + k1],
                         twiddle_c((c0*k1) & (N2L-1), N2L, -1.0f));
        float2 yb = cmul(sb[(2*half + 1)*CH + k1],
                         twiddle_c(((c0+1)*k1) & (N2L-1), N2L, -1.0f));
        *(float4*)&dA[k1 * 1024 + c0] = make_float4(ya.x, ya.y, yb.x, yb.y);
    }
}

// ---------------------------------------------------------------------------
// k4: paired rows (k1, 512-k1); fwd FFT1024 x2 via radix-2 split; Hermitian
//   pointwise S = U*Kd; REAL-OUTPUT fold to one FFT512 per slot + W_L
//   twiddle. STORE PAIR-TILED: dB[(m>>1)*1024 + kk*2 + (m&1)] so k5's
//   column-pair read is contiguous. grid=256, TPB=512.
// ---------------------------------------------------------------------------
#define TPB4 512
__global__ void __launch_bounds__(TPB4, 1)
k4_mega() {
    __shared__ __align__(16) float2 sa[4*CH], sb[4*CH];
    __shared__ float2 tw[512], twh[512];
    const int t = threadIdx.x;
    for (int i = t; i < 512; i += TPB4) { tw[i] = gtw512g[i]; twh[i] = gtw1024g[i]; }
    const int b = blockIdx.x;
    const int rowA = b;
    const int rowB = (b == 0) ? 256 : 512 - b;

    for (int i = t; i < 1024; i += TPB4) {
        int slot = i >> 9, m2 = i & 511;
        int row = slot ? rowB : rowA;
        float4 x = ((const float4*)(dA + row * 1024))[m2];
        *(float4*)&sb[slot * 1024 + 2*m2] = x;
    }
    __syncthreads();
    for (int i = t; i < 1024; i += TPB4) {
        int slot = i >> 9, m = i & 511;
        float2 a = sb[slot * 1024 + m];
        float2 c = sb[slot * 1024 + m + 512];
        sa[(slot*2 + 0)*CH + m] = cadd(a, c);
        sa[(slot*2 + 1)*CH + m] = cmul(csub(a, c), twh[m]);
    }
    __syncthreads();
    fft512q<-1>(sa, sb, t >> 7, t & 127, tw, true);
    for (int i = t; i < 2048; i += TPB4) {
        int fp = i >> 9, r = i & 511;
        int slot = fp >> 1, h = fp & 1;
        int k = 2*r + h;
        int pslot, pk_;
        if (b == 0) {
            pslot = slot;
            pk_ = slot ? (1023 - k) : ((1024 - k) & 1023);
        } else {
            pslot = 1 - slot;
            pk_ = 1023 - k;
        }
        float2 Zv = sb[fp*CH + r];
        float2 Zp = sb[(pslot*2 + (pk_ & 1))*CH + (pk_ >> 1)];
        float2 U  = make_float2(0.5f * (Zv.x + Zp.x),  0.5f * (Zv.y - Zp.y));
        float2 Kd = make_float2(0.5f * (Zv.y + Zp.y), -0.5f * (Zv.x - Zp.x));
        sa[fp*CH + r] = cmul(U, Kd);
    }
    __syncthreads();
    for (int i = t; i < 1024; i += TPB4) {
        int slot = i >> 9, kc = i & 511;
        int h = kc & 1, r0 = kc >> 1;
        int cb = (slot*2 + h)*CH;
        float2 S1 = sa[cb + r0];
        float2 S2 = sa[cb + r0 + 256];
        float2 E = make_float2(0.5f*(S1.x + S2.x), 0.5f*(S1.y + S2.y));
        float2 d = make_float2(0.5f*(S1.x - S2.x), 0.5f*(S1.y - S2.y));
        int kk = slot ? rowB : rowA;
        float2 o = cmul(twiddle_c(kk + (kc << 9), N2L, 1.0f), d);   // w^k * d
        sb[slot*CH + kc] = make_float2(E.x - o.y, E.y + o.x);       // E + i*O
    }
    __syncthreads();
    fft512q<+1>(sb, sa, t >> 7, t & 127, tw, t < 256);   // out sa chunks 0,1
    for (int i = t; i < 1024; i += TPB4) {
        int slot = i >> 9, m = i & 511;
        int kk = slot ? rowB : rowA;
        float2 val = cmul(sa[slot*CH + m],
                          twiddle_c((m*kk) & (L_SIZE-1), L_SIZE, 1.0f));
        dB[(m >> 1) * 1024 + kk * 2 + (m & 1)] = val;   // pair-tiled
    }
}

// ---------------------------------------------------------------------------
// k5: column-pair IFFT512 of the pair-tiled dB. Block bid = pair; its 1024
//   float2 (8KB) are CONTIGUOUS at dB + bid*1024: element kk*2 + j is
//   column (2bid+j), row kk. z2[p*512+m] = y[2n] + i y[2n+1]. grid=256.
// ---------------------------------------------------------------------------
#define TPB5 256
__global__ void __launch_bounds__(TPB5, 2)
k5_inv_cols(const float* __restrict__ u, const float* __restrict__ Dp,
            float* __restrict__ out) {
    __shared__ __align__(16) float2 sa[2*CH], sb[2*CH];
    __shared__ float2 tw[512];
    const int bid = blockIdx.x;
    const int m0 = bid * 2;
    const int t = threadIdx.x;
    for (int i = t; i < 512; i += TPB5) tw[i] = gtw512g[i];
    const float4* src = (const float4*)(dB + bid * 1024);   // contiguous 8KB
    for (int i = t; i < 512; i += TPB5) {
        float4 x = src[i];              // row kk=i: cols m0 (x,y), m0+1 (z,w)
        sa[0*CH + i] = make_float2(x.x, x.y);
        sa[1*CH + i] = make_float2(x.z, x.w);
    }
    __syncthreads();
    fft512q<+1>(sa, sb, t >> 7, t & 127, tw, true);
    const float sc = 1.0f / (float)L_SIZE;
    const float Dv = Dp[0];
    for (int p = t; p < 256; p += TPB5) {
        float2 v0 = sb[0*CH + p];
        float2 v1 = sb[1*CH + p];
        int n2 = 2 * (p * 512 + m0);
        float4 uu = *(const float4*)(u + n2);
        float4 o;
        o.x = fmaf(Dv, uu.x, v0.x * sc);
        o.y = fmaf(Dv, uu.y, v0.y * sc);
        o.z = fmaf(Dv, uu.z, v1.x * sc);
        o.w = fmaf(Dv, uu.w, v1.y * sc);
        *(float4*)(out + n2) = o;
    }
}

// ---------------------------------------------------------------------------
extern "C" void kernel_launch(void* const* d_in, const int* in_sizes, int n_in,
                              void* d_out, int out_size) {
    (void)in_sizes; (void)n_in; (void)out_size;
    const float* u   = (const float*)d_in[0];
    const float* Lre = (const float*)d_in[1];
    const float* Lim = (const float*)d_in[2];
    const float* Pre = (const float*)d_in[3];
    const float* Pim = (const float*)d_in[4];
    const float* Bre = (const float*)d_in[5];
    const float* Bim = (const float*)d_in[6];
    const float* Cri = (const float*)d_in[7];
    const float* Dp  = (const float*)d_in[8];
    const float* ls  = (const float*)d_in[9];
    float* out = (float*)d_out;

    k01_gen     <<<256, TPB01>>>(Lre, Lim, Pre, Pim, Bre, Bim, Cri, ls);
    k23_cols    <<<256, TPB23>>>(u);
    k4_mega     <<<256, TPB4>>>();
    k5_inv_cols <<<256, TPB5>>>(u, Dp, out);
}